// round 4
// baseline (speedup 1.0000x reference)
#include <cuda_runtime.h>

// MDN_module, fused single kernel, u64-packed f32x2 datapath.
// Inputs: x[B,2] y[B,1,2] eps[B,1,2] W1[2,64] b1[64] W2[64,4] b2[4] Wv[2,2]
// Output: fx (2B floats) then logp_y scalar at out[2B].

typedef unsigned long long u64;

#define HID 64
#define PAIRS 4            // row-pairs per thread per group (8 rows/group)
#define NTHREADS 256
#define MAXBLK 1024

__device__ double g_part[MAXBLK];
__device__ unsigned g_ticket = 0;

// ---- packed helpers: values stay in u64 register pairs, no per-call packing ----
__device__ __forceinline__ u64 ffma2(u64 a, u64 b, u64 c) {
    u64 d; asm("fma.rn.f32x2 %0, %1, %2, %3;" : "=l"(d) : "l"(a), "l"(b), "l"(c));
    return d;
}
__device__ __forceinline__ u64 relu2(u64 a) {
    u64 d;
    asm("{\n\t.reg .f32 lo, hi;\n\t"
        "mov.b64 {lo, hi}, %1;\n\t"
        "max.f32 lo, lo, 0f00000000;\n\t"
        "max.f32 hi, hi, 0f00000000;\n\t"
        "mov.b64 %0, {lo, hi};\n\t}"
        : "=l"(d) : "l"(a));
    return d;
}
__device__ __forceinline__ u64 pk2(float lo, float hi) {
    u64 r; asm("mov.b64 %0, {%1, %2};" : "=l"(r) : "f"(lo), "f"(hi)); return r;
}
__device__ __forceinline__ void upk2(float& lo, float& hi, u64 v) {
    asm("mov.b64 {%0, %1}, %2;" : "=f"(lo), "=f"(hi) : "l"(v));
}

// per-row epilogue: returns d0^2/v0 + d1^2/v1 + f2 + f3 ; writes fx0,fx1
__device__ __forceinline__ float row_tail(
    float x0, float x1, float mu0, float mu1, float f2, float f3,
    float y0, float y1, float e0, float e1,
    float wv00, float wv01, float wv10, float wv11,
    float& fx0, float& fx1)
{
    float z0 = fmaf(x0, wv00, x1 * wv10);
    float z1 = fmaf(x0, wv01, x1 * wv11);
    float Vx = fmaf(z0, z0, fmaf(z1, z1, 1e-3f));
    float m0 = fmaf(mu0, wv00, mu1 * wv10);
    float m1 = fmaf(mu0, wv01, mu1 * wv11);
    float Vmu = fmaf(m0, m0, fmaf(m1, m1, 1e-3f));
    // beta*Vx - relu(beta*Vx - Vmu) == min(beta*Vx, Vmu) exactly
    float scale = __fdividef(fminf(0.99f * Vx, Vmu), Vmu);
    float ms0 = mu0 * scale;
    float ms1 = mu1 * scale;
    float v0 = __expf(f2);
    float v1 = __expf(f3);
    float r0 = rsqrtf(v0);
    float r1 = rsqrtf(v1);
    fx0 = fmaf(v0 * r0, e0, ms0);
    fx1 = fmaf(v1 * r1, e1, ms1);
    float d0 = y0 - ms0;
    float d1 = y1 - ms1;
    float s = fmaf(d0 * d0, r0 * r0, f2 + f3);   // log v0 + log v1 == f2 + f3 exactly
    s = fmaf(d1 * d1, r1 * r1, s);
    return s;
}

__global__ void __launch_bounds__(NTHREADS, 3)
mdn_fused(const float4* __restrict__ x4, const float4* __restrict__ y4,
          const float4* __restrict__ e4,
          const float* __restrict__ W1, const float* __restrict__ b1,
          const float* __restrict__ W2, const float* __restrict__ b2,
          const float* __restrict__ Wv,
          float4* __restrict__ o4, float* __restrict__ out,
          int nGroups, long long B)
{
    // per-neuron packed weights (u64 pairs): [w0, w1, bb, c0, c1, c2, c3, pad] = 64B row
    __shared__ u64 swq[HID][8];
    __shared__ double sred[NTHREADS];

    int t = threadIdx.x;
    if (t < HID) {
        float w0 = W1[t], w1 = W1[HID + t], b = b1[t];
        swq[t][0] = pk2(w0, w0);
        swq[t][1] = pk2(w1, w1);
        swq[t][2] = pk2(b, b);
#pragma unroll
        for (int k = 0; k < 4; k++) {
            float w = W2[t * 4 + k];
            swq[t][3 + k] = pk2(w, w);
        }
        swq[t][7] = 0ull;
    }
    __syncthreads();

    float wv00 = Wv[0], wv01 = Wv[1], wv10 = Wv[2], wv11 = Wv[3];
    u64 pb0 = pk2(b2[0], b2[0]);
    u64 pb1 = pk2(b2[1], b2[1]);
    u64 pb2_ = pk2(b2[2], b2[2]);
    u64 pb3 = pk2(b2[3], b2[3]);

    float lsum = 0.0f;
    int tid = blockIdx.x * blockDim.x + threadIdx.x;
    int stride = gridDim.x * blockDim.x;

    for (int g = tid; g < nGroups; g += stride) {
        int base = g * PAIRS;
        u64 X0[PAIRS], X1[PAIRS];
        u64 a0[PAIRS], a1[PAIRS], a2[PAIRS], a3[PAIRS];
#pragma unroll
        for (int p = 0; p < PAIRS; p++) {
            float4 xv = x4[base + p];              // {x0_a, x1_a, x0_b, x1_b}
            X0[p] = pk2(xv.x, xv.z);
            X1[p] = pk2(xv.y, xv.w);
            a0[p] = pb0; a1[p] = pb1; a2[p] = pb2_; a3[p] = pb3;
        }

#pragma unroll 4
        for (int j = 0; j < HID; j++) {
            const ulonglong2* row = (const ulonglong2*)swq[j];
            ulonglong2 q0 = row[0];                // {w0, w1}
            ulonglong2 q1 = row[1];                // {bb, c0}
            ulonglong2 q2 = row[2];                // {c1, c2}
            ulonglong2 q3 = row[3];                // {c3, pad}
#pragma unroll
            for (int p = 0; p < PAIRS; p++) {
                u64 pre = ffma2(X1[p], q0.y, q1.x);
                pre = ffma2(X0[p], q0.x, pre);
                u64 h = relu2(pre);
                a0[p] = ffma2(h, q1.y, a0[p]);
                a1[p] = ffma2(h, q2.x, a1[p]);
                a2[p] = ffma2(h, q2.y, a2[p]);
                a3[p] = ffma2(h, q3.x, a3[p]);
            }
        }

#pragma unroll
        for (int p = 0; p < PAIRS; p++) {
            float f0a, f0b, f1a, f1b, f2a, f2b, f3a, f3b;
            upk2(f0a, f0b, a0[p]);
            upk2(f1a, f1b, a1[p]);
            upk2(f2a, f2b, a2[p]);
            upk2(f3a, f3b, a3[p]);
            float x0a, x0b, x1a, x1b;
            upk2(x0a, x0b, X0[p]);
            upk2(x1a, x1b, X1[p]);
            float4 yv = y4[base + p];
            float4 ev = e4[base + p];
            float fa0, fa1, fb0, fb1;
            lsum += row_tail(x0a, x1a, f0a, f1a, f2a, f3a, yv.x, yv.y, ev.x, ev.y,
                             wv00, wv01, wv10, wv11, fa0, fa1);
            lsum += row_tail(x0b, x1b, f0b, f1b, f2b, f3b, yv.z, yv.w, ev.z, ev.w,
                             wv00, wv01, wv10, wv11, fb0, fb1);
            float4 o; o.x = fa0; o.y = fa1; o.z = fb0; o.w = fb1;
            o4[base + p] = o;
        }
    }

    // tail rows not covered by 8-row groups (B here is a multiple of 8; kept for safety)
    long long startRow = (long long)nGroups * 8;
    if (blockIdx.x == 0 && startRow + threadIdx.x < B) {
        long long r = startRow + threadIdx.x;
        const float* x = (const float*)x4;
        const float* y = (const float*)y4;
        const float* e = (const float*)e4;
        float x0 = x[2 * r], x1 = x[2 * r + 1];
        float f0 = b2[0], f1 = b2[1], f2 = b2[2], f3 = b2[3];
        for (int j = 0; j < HID; j++) {
            float h = fmaxf(fmaf(x0, W1[j], fmaf(x1, W1[HID + j], b1[j])), 0.0f);
            f0 = fmaf(h, W2[j * 4 + 0], f0);
            f1 = fmaf(h, W2[j * 4 + 1], f1);
            f2 = fmaf(h, W2[j * 4 + 2], f2);
            f3 = fmaf(h, W2[j * 4 + 3], f3);
        }
        float fx0, fx1;
        lsum += row_tail(x0, x1, f0, f1, f2, f3,
                         y[2 * r], y[2 * r + 1], e[2 * r], e[2 * r + 1],
                         wv00, wv01, wv10, wv11, fx0, fx1);
        ((float*)o4)[2 * r] = fx0;
        ((float*)o4)[2 * r + 1] = fx1;
    }

    // deterministic block tree reduction -> per-block double partial
    sred[threadIdx.x] = (double)lsum;
    __syncthreads();
#pragma unroll
    for (int off = NTHREADS / 2; off > 0; off >>= 1) {
        if (threadIdx.x < off) sred[threadIdx.x] += sred[threadIdx.x + off];
        __syncthreads();
    }
    if (threadIdx.x == 0) g_part[blockIdx.x] = sred[0];

    // last-block finalize
    __shared__ bool is_last;
    __threadfence();
    if (threadIdx.x == 0) {
        unsigned prev = atomicAdd(&g_ticket, 1u);
        is_last = (prev == gridDim.x - 1);
    }
    __syncthreads();
    if (is_last) {
        double v = 0.0;
        for (int i = threadIdx.x; i < gridDim.x; i += NTHREADS) v += g_part[i];
        sred[threadIdx.x] = v;
        __syncthreads();
#pragma unroll
        for (int off = NTHREADS / 2; off > 0; off >>= 1) {
            if (threadIdx.x < off) sred[threadIdx.x] += sred[threadIdx.x + off];
            __syncthreads();
        }
        if (threadIdx.x == 0) {
            out[2 * B] = (float)(0.5 * sred[0] + (double)B * 1.8378770664093453);
            g_ticket = 0;   // reset for next graph replay
        }
    }
}

extern "C" void kernel_launch(void* const* d_in, const int* in_sizes, int n_in,
                              void* d_out, int out_size)
{
    const float* x  = (const float*)d_in[0];
    const float* y  = (const float*)d_in[1];
    const float* e  = (const float*)d_in[2];
    const float* W1 = (const float*)d_in[3];
    const float* b1 = (const float*)d_in[4];
    const float* W2 = (const float*)d_in[5];
    const float* b2 = (const float*)d_in[6];
    const float* Wv = (const float*)d_in[7];
    float* out = (float*)d_out;

    long long B = (long long)in_sizes[0] / 2;
    int nGroups = (int)(B / 8);

    int blocks = 456;                    // 3 per SM (152 SMs), persistent grid-stride
    if (blocks > MAXBLK) blocks = MAXBLK;

    mdn_fused<<<blocks, NTHREADS>>>((const float4*)x, (const float4*)y,
                                    (const float4*)e, W1, b1, W2, b2, Wv,
                                    (float4*)out, out, nGroups, B);
}

// round 5
// speedup vs baseline: 1.5465x; 1.5465x over previous
#include <cuda_runtime.h>

// MDN_module, fused single kernel, u64-packed f32x2 datapath, mov-free relu.
// Inputs: x[B,2] y[B,1,2] eps[B,1,2] W1[2,64] b1[64] W2[64,4] b2[4] Wv[2,2]
// Output: fx (2B floats) then logp_y scalar at out[2B].

typedef unsigned long long u64;

#define HID 64
#define PAIRS 2            // row-pairs per thread per group (4 rows/group)
#define NTHREADS 128
#define MAXBLK 2048

__device__ double g_part[MAXBLK];
__device__ unsigned g_ticket = 0;

// ---- packed helpers: values stay in u64 register pairs ----
__device__ __forceinline__ u64 ffma2(u64 a, u64 b, u64 c) {
    u64 d; asm("fma.rn.f32x2 %0, %1, %2, %3;" : "=l"(d) : "l"(a), "l"(b), "l"(c));
    return d;
}
__device__ __forceinline__ u64 fadd2(u64 a, u64 b) {
    u64 d; asm("add.rn.f32x2 %0, %1, %2;" : "=l"(d) : "l"(a), "l"(b));
    return d;
}
__device__ __forceinline__ u64 pk2(float lo, float hi) {
    u64 r; asm("mov.b64 %0, {%1, %2};" : "=l"(r) : "f"(lo), "f"(hi)); return r;
}
__device__ __forceinline__ void upk2(float& lo, float& hi, u64 v) {
    asm("mov.b64 {%0, %1}, %2;" : "=f"(lo), "=f"(hi) : "l"(v));
}

// per-row epilogue: returns d0^2/v0 + d1^2/v1 + f2 + f3 ; writes fx0,fx1
__device__ __forceinline__ float row_tail(
    float x0, float x1, float mu0, float mu1, float f2, float f3,
    float y0, float y1, float e0, float e1,
    float wv00, float wv01, float wv10, float wv11,
    float& fx0, float& fx1)
{
    float z0 = fmaf(x0, wv00, x1 * wv10);
    float z1 = fmaf(x0, wv01, x1 * wv11);
    float Vx = fmaf(z0, z0, fmaf(z1, z1, 1e-3f));
    float m0 = fmaf(mu0, wv00, mu1 * wv10);
    float m1 = fmaf(mu0, wv01, mu1 * wv11);
    float Vmu = fmaf(m0, m0, fmaf(m1, m1, 1e-3f));
    // beta*Vx - relu(beta*Vx - Vmu) == min(beta*Vx, Vmu) exactly
    float scale = __fdividef(fminf(0.99f * Vx, Vmu), Vmu);
    float ms0 = mu0 * scale;
    float ms1 = mu1 * scale;
    float v0 = __expf(f2);
    float v1 = __expf(f3);
    float r0 = rsqrtf(v0);
    float r1 = rsqrtf(v1);
    fx0 = fmaf(v0 * r0, e0, ms0);
    fx1 = fmaf(v1 * r1, e1, ms1);
    float d0 = y0 - ms0;
    float d1 = y1 - ms1;
    float s = fmaf(d0 * d0, r0 * r0, f2 + f3);   // log v0 + log v1 == f2 + f3 exactly
    s = fmaf(d1 * d1, r1 * r1, s);
    return s;
}

__global__ void __launch_bounds__(NTHREADS, 7)
mdn_fused(const float4* __restrict__ x4, const float4* __restrict__ y4,
          const float4* __restrict__ e4,
          const float* __restrict__ W1, const float* __restrict__ b1,
          const float* __restrict__ W2, const float* __restrict__ b2,
          const float* __restrict__ Wv,
          float4* __restrict__ o4, float* __restrict__ out,
          int nGroups, long long B)
{
    // per-neuron packed weights (u64 pairs): [w0, w1, bb, c0/2, c1/2, c2/2, c3/2, pad]
    __shared__ u64 swq[HID][8];
    __shared__ double sred[NTHREADS];

    int t = threadIdx.x;
    if (t < HID) {
        float w0 = W1[t], w1 = W1[HID + t], b = b1[t];
        swq[t][0] = pk2(w0, w0);
        swq[t][1] = pk2(w1, w1);
        swq[t][2] = pk2(b, b);
#pragma unroll
        for (int k = 0; k < 4; k++) {
            float w = 0.5f * W2[t * 4 + k];        // fold relu's /2 into W2
            swq[t][3 + k] = pk2(w, w);
        }
        swq[t][7] = 0ull;
    }
    __syncthreads();

    float wv00 = Wv[0], wv01 = Wv[1], wv10 = Wv[2], wv11 = Wv[3];
    u64 pb0 = pk2(b2[0], b2[0]);
    u64 pb1 = pk2(b2[1], b2[1]);
    u64 pb2_ = pk2(b2[2], b2[2]);
    u64 pb3 = pk2(b2[3], b2[3]);
    const u64 ABS2 = 0x7FFFFFFF7FFFFFFFULL;

    float lsum = 0.0f;
    int tid = blockIdx.x * blockDim.x + threadIdx.x;
    int stride = gridDim.x * blockDim.x;

    for (int g = tid; g < nGroups; g += stride) {
        int base = g * PAIRS;
        u64 X0[PAIRS], X1[PAIRS];
        u64 a0[PAIRS], a1[PAIRS], a2[PAIRS], a3[PAIRS];
#pragma unroll
        for (int p = 0; p < PAIRS; p++) {
            float4 xv = x4[base + p];              // {x0_a, x1_a, x0_b, x1_b}
            X0[p] = pk2(xv.x, xv.z);
            X1[p] = pk2(xv.y, xv.w);
            a0[p] = pb0; a1[p] = pb1; a2[p] = pb2_; a3[p] = pb3;
        }

#pragma unroll 8
        for (int j = 0; j < HID; j++) {
            const ulonglong2* row = (const ulonglong2*)swq[j];
            ulonglong2 q0 = row[0];                // {w0, w1}
            ulonglong2 q1 = row[1];                // {bb, c0/2}
            ulonglong2 q2 = row[2];                // {c1/2, c2/2}
            ulonglong2 q3 = row[3];                // {c3/2, pad}
#pragma unroll
            for (int p = 0; p < PAIRS; p++) {
                u64 pre = ffma2(X1[p], q0.y, q1.x);
                pre = ffma2(X0[p], q0.x, pre);
                // 2*relu(pre) = pre + |pre|  (exact; /2 folded into c_k)
                u64 h2 = fadd2(pre, pre & ABS2);   // 2x LOP3 on pair halves + ADD2
                a0[p] = ffma2(h2, q1.y, a0[p]);
                a1[p] = ffma2(h2, q2.x, a1[p]);
                a2[p] = ffma2(h2, q2.y, a2[p]);
                a3[p] = ffma2(h2, q3.x, a3[p]);
            }
        }

#pragma unroll
        for (int p = 0; p < PAIRS; p++) {
            float f0a, f0b, f1a, f1b, f2a, f2b, f3a, f3b;
            upk2(f0a, f0b, a0[p]);
            upk2(f1a, f1b, a1[p]);
            upk2(f2a, f2b, a2[p]);
            upk2(f3a, f3b, a3[p]);
            float x0a, x0b, x1a, x1b;
            upk2(x0a, x0b, X0[p]);
            upk2(x1a, x1b, X1[p]);
            float4 yv = y4[base + p];
            float4 ev = e4[base + p];
            float fa0, fa1, fb0, fb1;
            lsum += row_tail(x0a, x1a, f0a, f1a, f2a, f3a, yv.x, yv.y, ev.x, ev.y,
                             wv00, wv01, wv10, wv11, fa0, fa1);
            lsum += row_tail(x0b, x1b, f0b, f1b, f2b, f3b, yv.z, yv.w, ev.z, ev.w,
                             wv00, wv01, wv10, wv11, fb0, fb1);
            float4 o; o.x = fa0; o.y = fa1; o.z = fb0; o.w = fb1;
            o4[base + p] = o;
        }
    }

    // tail rows not covered by 4-row groups (none for this B; kept for safety)
    long long startRow = (long long)nGroups * (2 * PAIRS);
    if (blockIdx.x == 0 && startRow + threadIdx.x < B) {
        long long r = startRow + threadIdx.x;
        const float* x = (const float*)x4;
        const float* y = (const float*)y4;
        const float* e = (const float*)e4;
        float x0 = x[2 * r], x1 = x[2 * r + 1];
        float f0 = b2[0], f1 = b2[1], f2 = b2[2], f3 = b2[3];
        for (int j = 0; j < HID; j++) {
            float h = fmaxf(fmaf(x0, W1[j], fmaf(x1, W1[HID + j], b1[j])), 0.0f);
            f0 = fmaf(h, W2[j * 4 + 0], f0);
            f1 = fmaf(h, W2[j * 4 + 1], f1);
            f2 = fmaf(h, W2[j * 4 + 2], f2);
            f3 = fmaf(h, W2[j * 4 + 3], f3);
        }
        float fx0, fx1;
        lsum += row_tail(x0, x1, f0, f1, f2, f3,
                         y[2 * r], y[2 * r + 1], e[2 * r], e[2 * r + 1],
                         wv00, wv01, wv10, wv11, fx0, fx1);
        ((float*)o4)[2 * r] = fx0;
        ((float*)o4)[2 * r + 1] = fx1;
    }

    // deterministic block tree reduction -> per-block double partial
    sred[threadIdx.x] = (double)lsum;
    __syncthreads();
#pragma unroll
    for (int off = NTHREADS / 2; off > 0; off >>= 1) {
        if (threadIdx.x < off) sred[threadIdx.x] += sred[threadIdx.x + off];
        __syncthreads();
    }
    if (threadIdx.x == 0) g_part[blockIdx.x] = sred[0];

    // last-block finalize
    __shared__ bool is_last;
    __threadfence();
    if (threadIdx.x == 0) {
        unsigned prev = atomicAdd(&g_ticket, 1u);
        is_last = (prev == gridDim.x - 1);
    }
    __syncthreads();
    if (is_last) {
        double v = 0.0;
        for (int i = threadIdx.x; i < gridDim.x; i += NTHREADS) v += g_part[i];
        sred[threadIdx.x] = v;
        __syncthreads();
#pragma unroll
        for (int off = NTHREADS / 2; off > 0; off >>= 1) {
            if (threadIdx.x < off) sred[threadIdx.x] += sred[threadIdx.x + off];
            __syncthreads();
        }
        if (threadIdx.x == 0) {
            out[2 * B] = (float)(0.5 * sred[0] + (double)B * 1.8378770664093453);
            g_ticket = 0;   // reset for next graph replay
        }
    }
}

extern "C" void kernel_launch(void* const* d_in, const int* in_sizes, int n_in,
                              void* d_out, int out_size)
{
    const float* x  = (const float*)d_in[0];
    const float* y  = (const float*)d_in[1];
    const float* e  = (const float*)d_in[2];
    const float* W1 = (const float*)d_in[3];
    const float* b1 = (const float*)d_in[4];
    const float* W2 = (const float*)d_in[5];
    const float* b2 = (const float*)d_in[6];
    const float* Wv = (const float*)d_in[7];
    float* out = (float*)d_out;

    long long B = (long long)in_sizes[0] / 2;
    int nGroups = (int)(B / (2 * PAIRS));

    int blocks = 152 * 7;                // persistent, 7 blocks/SM target
    if (blocks > MAXBLK) blocks = MAXBLK;

    mdn_fused<<<blocks, NTHREADS>>>((const float4*)x, (const float4*)y,
                                    (const float4*)e, W1, b1, W2, b2, Wv,
                                    (float4*)out, out, nGroups, B);
}